// round 4
// baseline (speedup 1.0000x reference)
#include <cuda_runtime.h>
#include <cuda_bf16.h>
#include <stdint.h>

// ---------------------------------------------------------------------------
// AggregationLayer: out[s,:] = mean over edges e with segment_ids[e]==s of
//                   values[gather_idx[e], :]
//   values:      [N_SRC=1e6, 64] f32
//   gather_idx:  [E=4e6] i64 (or i32) -- random in [0, N_SRC)
//   segment_ids: [E] i64/i32 -- SORTED ascending
//   out:         [S=250e3, 64] f32  (mean per segment; empty segment -> 0)
//
// R3 (resubmit after infra flake): 2 kernels only (dtype probe inlined),
// 2 segments per warp with float4 lanes (16 lanes per row) for 2x MLP,
// unroll 8.
// ---------------------------------------------------------------------------

#define D 64
#define MAX_SEGS (1 << 20)

__device__ int g_seg_start[MAX_SEGS + 1];

// int64 little-endian indices < 2^32 => odd 32-bit words are all zero.
// For int32 data those words are random values in [0, N_SRC): P(all 0) ~ 0.
__device__ __forceinline__ int probe_is64(const unsigned int* w) {
    return (w[1] == 0u) & (w[3] == 0u) & (w[5] == 0u) & (w[7] == 0u);
}

// --- build seg_start[0..S] : lower-bound offsets into the edge array --------
template <typename IdxT>
__device__ __forceinline__ void fill_impl(const IdxT* __restrict__ segs,
                                          long long E, int S) {
    long long e = (long long)blockIdx.x * blockDim.x + threadIdx.x;
    if (e > E) return;
    if (e == E) {
        int last = (int)segs[E - 1];
        for (int t = last + 1; t <= S; ++t) g_seg_start[t] = (int)E;
        return;
    }
    int s  = (int)segs[e];
    int sp = (e == 0) ? -1 : (int)segs[e - 1];
    for (int t = sp + 1; t <= s; ++t) g_seg_start[t] = (int)e;
}

__global__ void fill_kernel(const void* __restrict__ segs,
                            const unsigned int* __restrict__ gi_words,
                            long long E, int S) {
    if (probe_is64(gi_words))
        fill_impl<long long>((const long long*)segs, E, S);
    else
        fill_impl<int>((const int*)segs, E, S);
}

// --- aggregation: 2 segments per warp, float4 per lane ----------------------
template <typename IdxT>
__device__ __forceinline__ void agg_impl(const float* __restrict__ values,
                                         const IdxT* __restrict__ gidx,
                                         float* __restrict__ out, int S) {
    const int lane = threadIdx.x & 31;
    const int hl   = lane & 15;              // lane within 16-lane half
    const int half = lane >> 4;              // 0 or 1
    const int warp = (int)((blockIdx.x * blockDim.x + threadIdx.x) >> 5);
    const int seg  = warp * 2 + half;
    if (seg >= S) return;

    const int b   = g_seg_start[seg];
    const int e2  = g_seg_start[seg + 1];
    const int cnt = e2 - b;

    float ax = 0.0f, ay = 0.0f, az = 0.0f, aw = 0.0f;
    const int col = hl * 4;

    for (int base = b; base < e2; base += 16) {
        const int m = min(16, e2 - base);
        // cooperative index load within the half (coalesced)
        long long my_idx = (hl < m) ? (long long)gidx[base + hl] : 0;
        #pragma unroll 8
        for (int j = 0; j < m; ++j) {
            // broadcast from lane (half*16 + j) within each 16-lane group
            const long long idx = __shfl_sync(0xffffffffu, my_idx, j, 16);
            const float4 v =
                *(const float4*)(values + idx * (long long)D + col);
            ax += v.x; ay += v.y; az += v.z; aw += v.w;
        }
    }

    const float inv = (cnt > 0) ? (1.0f / (float)cnt) : 0.0f;
    float4 r;
    r.x = ax * inv; r.y = ay * inv; r.z = az * inv; r.w = aw * inv;
    *(float4*)(out + (long long)seg * D + col) = r;
}

__global__ void agg_kernel(const float* __restrict__ values,
                           const void* __restrict__ gidx,
                           float* __restrict__ out, int S) {
    if (probe_is64((const unsigned int*)gidx))
        agg_impl<long long>(values, (const long long*)gidx, out, S);
    else
        agg_impl<int>(values, (const int*)gidx, out, S);
}

// ---------------------------------------------------------------------------
extern "C" void kernel_launch(void* const* d_in, const int* in_sizes, int n_in,
                              void* d_out, int out_size) {
    const float* values = (const float*)d_in[0];
    const void*  gidx   = d_in[1];
    const void*  segs   = d_in[2];
    float*       out    = (float*)d_out;

    const long long E = (long long)in_sizes[1];
    const int       S = (int)((long long)out_size / D);

    // 1) segment offset table from sorted segment_ids
    {
        const int threads = 256;
        const long long blocks = (E + 1 + threads - 1) / threads;
        fill_kernel<<<(unsigned)blocks, threads>>>(
            segs, (const unsigned int*)gidx, E, S);
    }

    // 2) gather + segmented mean: warp handles 2 segments, float4 lanes
    {
        const int threads = 256;                  // 8 warps -> 16 segments/block
        const int blocks  = (S + 15) / 16;
        agg_kernel<<<blocks, threads>>>(values, gidx, out, S);
    }
}